// round 15
// baseline (speedup 1.0000x reference)
#include <cuda_runtime.h>
#include <cstdint>

// STFT via 2048-pt complex FFT (two real frames per FFT: A=re, B=im).
// DIF radix 8-8-8-4, XOR-swizzled 16KB smem buffer, fused conjugate-split
// epilogue, packed f32x2 add/sub. R14 = R9 (best measured) +
//  - window via direct 2-FFMA per j (replaces serial pi/4 rotation chain)
//  - twiddle powers via bounded-liveness product tree (depth 3, not 6)
// Structural experiments R11-R13 (multi-FFT CTAs, twiddle table, carveout)
// all regressed and are reverted.

#define WINDOW   2048
#define STRIDE   512
#define FREQ     1024
#define FRAMES   63
#define SIG_LEN  32256
#define BATCH    64
#define PAD_L    768
#define NT       256
#define NPAIRS   ((BATCH * FRAMES) / 2)   // 2016

// Packed complex add/sub: one f32x2 op instead of two FADD.
__device__ __forceinline__ float2 cadd(float2 a, float2 b) {
    float2 r;
    asm("{\n\t.reg .b64 ra, rb, rc;\n\t"
        "mov.b64 ra, {%2, %3};\n\t"
        "mov.b64 rb, {%4, %5};\n\t"
        "add.rn.f32x2 rc, ra, rb;\n\t"
        "mov.b64 {%0, %1}, rc;\n\t}"
        : "=f"(r.x), "=f"(r.y)
        : "f"(a.x), "f"(a.y), "f"(b.x), "f"(b.y));
    return r;
}
__device__ __forceinline__ float2 csub(float2 a, float2 b) {
    float2 r;
    asm("{\n\t.reg .b64 ra, rb, rc;\n\t"
        "mov.b64 ra, {%2, %3};\n\t"
        "mov.b64 rb, {%4, %5};\n\t"
        "sub.rn.f32x2 rc, ra, rb;\n\t"
        "mov.b64 {%0, %1}, rc;\n\t}"
        : "=f"(r.x), "=f"(r.y)
        : "f"(a.x), "f"(a.y), "f"(b.x), "f"(b.y));
    return r;
}
__device__ __forceinline__ float2 cmul(float2 a, float2 b) {
    return make_float2(fmaf(a.x, b.x, -a.y * b.y), fmaf(a.x, b.y, a.y * b.x));
}
__device__ __forceinline__ float2 cnegi(float2 a) { return make_float2(a.y, -a.x); }  // a * (-i)

// Logical swizzle: sw(k) = k ^ ((((k>>5)^(k>>8))&7)<<2), applied per pass
// algebraically with XOR (slots hoisted).

// In-place 8-point DFT: E[q] = sum_j E_in[j] * exp(-2*pi*i*j*q/8)
__device__ __forceinline__ void dft8(float2* E) {
    const float R = 0.70710678118654752440f;
    float2 s0 = cadd(E[0], E[4]), s1 = cadd(E[1], E[5]);
    float2 s2 = cadd(E[2], E[6]), s3 = cadd(E[3], E[7]);
    float2 d0 = csub(E[0], E[4]), d1 = csub(E[1], E[5]);
    float2 d2 = csub(E[2], E[6]), d3 = csub(E[3], E[7]);
    d1 = make_float2(R * (d1.x + d1.y), R * (d1.y - d1.x));
    d2 = cnegi(d2);
    d3 = make_float2(R * (d3.y - d3.x), -R * (d3.x + d3.y));
    float2 A0 = cadd(s0, s2), A1 = cadd(s1, s3);
    float2 B0 = csub(s0, s2), B1 = cnegi(csub(s1, s3));
    E[0] = cadd(A0, A1); E[2] = cadd(B0, B1);
    E[4] = csub(A0, A1); E[6] = csub(B0, B1);
    float2 C0 = cadd(d0, d2), C1 = cadd(d1, d3);
    float2 D0 = csub(d0, d2), D1 = cnegi(csub(d1, d3));
    E[1] = cadd(C0, C1); E[3] = cadd(D0, D1);
    E[5] = csub(C0, C1); E[7] = csub(D0, D1);
}

__device__ __forceinline__ void dft4(float2* F) {
    float2 A0 = cadd(F[0], F[2]), A1 = cadd(F[1], F[3]);
    float2 B0 = csub(F[0], F[2]), B1 = cnegi(csub(F[1], F[3]));
    F[0] = cadd(A0, A1); F[1] = cadd(B0, B1);
    F[2] = csub(A0, A1); F[3] = csub(B0, B1);
}

// Store E[q]*w1^q at zz[idx[q]]: bounded-liveness power tree (depth 3,
// peak 4 live twiddles), stores issued as powers become ready.
__device__ __forceinline__ void twiddle_store(float2* zz, const float2* E,
                                              const int* idx, float2 w1) {
    zz[idx[0]] = E[0];
    zz[idx[1]] = cmul(E[1], w1);
    float2 w2 = cmul(w1, w1);
    zz[idx[2]] = cmul(E[2], w2);
    float2 w3 = cmul(w2, w1);
    zz[idx[3]] = cmul(E[3], w3);
    float2 w4 = cmul(w2, w2);
    zz[idx[4]] = cmul(E[4], w4);
    float2 w6 = cmul(w3, w3);
    zz[idx[6]] = cmul(E[6], w6);
    zz[idx[5]] = cmul(E[5], cmul(w4, w1));
    zz[idx[7]] = cmul(E[7], cmul(w6, w1));
}

__global__ __launch_bounds__(NT, 7) void stft_kernel(const float* __restrict__ x,
                                                     float* __restrict__ out)
{
    __shared__ __align__(16) float2 zz[2048];

    const int t = threadIdx.x;
    const int pr = blockIdx.x;
    const int m0 = 2 * pr, m1 = m0 + 1;
    const int ba = m0 / FRAMES, fa = m0 - ba * FRAMES;
    const int bb = m1 / FRAMES, fb = m1 - bb * FRAMES;
    const float* xA = x + ba * SIG_LEN;
    const float* xB = x + bb * SIG_LEN;
    const int baseA = fa * STRIDE - PAD_L;
    const int baseB = fb * STRIDE - PAD_L;

    float2 E[8];
    int idx[8];

    // ---- pass 0 (DIF, N=2048, M=256): coalesced gmem loads x[t+256j],
    // half-Hann (0.5x folded from epilogue) via direct FFMA form, DFT8
    // over j, twiddle W_2048^(t*q), store block q. sw slot: (t>>5) ^ q.
    {
        float sn0, cs0;
        __sincosf(3.06796157577128245e-3f * (float)t, &sn0, &cs0);  // 2*pi*t/2048

        float va[8], vb[8];
        const bool interior = (baseA >= 0) && (baseA <= SIG_LEN - WINDOW) &&
                              (baseB >= 0) && (baseB <= SIG_LEN - WINDOW);
        if (interior) {
            #pragma unroll
            for (int j = 0; j < 8; j++) {
                va[j] = xA[baseA + t + 256 * j];
                vb[j] = xB[baseB + t + 256 * j];
            }
        } else {
            #pragma unroll
            for (int j = 0; j < 8; j++) {
                int ia = baseA + t + 256 * j;
                int ib = baseB + t + 256 * j;
                va[j] = ((unsigned)ia < (unsigned)SIG_LEN) ? xA[ia] : 0.0f;
                vb[j] = ((unsigned)ib < (unsigned)SIG_LEN) ? xB[ib] : 0.0f;
            }
        }

        // 0.5*hann(t+256j) = 0.25 - 0.25*cos(theta + j*pi/4)
        //                  = 0.25 - 0.25*(cs0*c_j - sn0*s_j)
        // with (c_j, s_j) = (cos, sin)(j*pi/4); independent 2-FFMA per j.
        const float RQ = 0.17677669529663688110f;   // 0.25 / sqrt(2)
        float w[4];
        w[0] = fmaf(cs0, -0.25f, 0.25f);                       // j=0
        w[1] = fmaf(sn0,  RQ,    fmaf(cs0, -RQ, 0.25f));       // j=1
        w[2] = fmaf(sn0,  0.25f, 0.25f);                       // j=2
        w[3] = fmaf(sn0,  RQ,    fmaf(cs0,  RQ, 0.25f));       // j=3
        #pragma unroll
        for (int j = 0; j < 4; j++) {
            float w0 = w[j];
            float w1 = 0.5f - w0;   // 0.5*hann(t + 256j + 1024)
            E[j]     = make_float2(w0 * va[j],     w0 * vb[j]);
            E[j + 4] = make_float2(w1 * va[j + 4], w1 * vb[j + 4]);
        }
        dft8(E);
        int s5 = t >> 5;
        #pragma unroll
        for (int q = 0; q < 8; q++) idx[q] = (t + 256 * q) ^ ((s5 ^ q) << 2);
        twiddle_store(zz, E, idx, make_float2(cs0, -sn0));  // W_2048^t
    }
    __syncthreads();

    // ---- pass 1 (N=256, M=32): warp q owns 256-block q; intra-warp.
    // sw slot for k=q*256+n2+32j: q ^ j.
    {
        int n2 = t & 31, q = t >> 5;
        int base = q * 256 + n2;
        #pragma unroll
        for (int j = 0; j < 8; j++) idx[j] = (base + 32 * j) ^ ((q ^ j) << 2);
        #pragma unroll
        for (int j = 0; j < 8; j++) E[j] = zz[idx[j]];
        dft8(E);
        float2 w1; __sincosf(-2.45436926061702597e-2f * (float)n2, &w1.y, &w1.x); // W_256^n2
        twiddle_store(zz, E, idx, w1);
    }
    __syncwarp();

    // ---- pass 2 (N=32, M=4): 4 threads per 32-block, intra-warp.
    // slot (b^(b>>3))&7 constant over j -> idx = b*32 + n3 + 4*(j^slot).
    {
        int n3 = t & 3, b = t >> 2;
        int slot = (b ^ (b >> 3)) & 7;
        int base = b * 32 + n3;
        #pragma unroll
        for (int j = 0; j < 8; j++) idx[j] = base + 4 * (j ^ slot);
        #pragma unroll
        for (int j = 0; j < 8; j++) E[j] = zz[idx[j]];
        dft8(E);
        float2 w1; __sincosf(-1.96349540849362077e-1f * (float)n3, &w1.y, &w1.x); // W_32^n3
        twiddle_store(zz, E, idx, w1);
    }
    __syncthreads();

    // ---- pass 3 (N=4) + fused conjugate-split epilogue.
    // f = 512*q3 + c, group g = digitrev8(c), element 4g+q3; slot per group
    // constant -> base 4*(g^slot), 16B-aligned. Values pre-scaled by 0.5:
    //   S = Zf + Zg = (outRA, outRB),  D = Zg - Zf = (outIB, -outIA).
    {
        int ca = t;
        int cb = t ? (512 - t) : 256;
        int ga = ((ca & 7) << 6) | (ca & 56) | (ca >> 6);
        int gb = ((cb & 7) << 6) | (cb & 56) | (cb >> 6);
        float2 G[4], H[4];
        {
            int ia = 4 * (ga ^ (((ga >> 3) ^ (ga >> 6)) & 7));
            float4 v0 = *(const float4*)&zz[ia];
            float4 v1 = *(const float4*)&zz[ia + 2];
            G[0] = make_float2(v0.x, v0.y); G[1] = make_float2(v0.z, v0.w);
            G[2] = make_float2(v1.x, v1.y); G[3] = make_float2(v1.z, v1.w);
            int ib = 4 * (gb ^ (((gb >> 3) ^ (gb >> 6)) & 7));
            float4 u0 = *(const float4*)&zz[ib];
            float4 u1 = *(const float4*)&zz[ib + 2];
            H[0] = make_float2(u0.x, u0.y); H[1] = make_float2(u0.z, u0.w);
            H[2] = make_float2(u1.x, u1.y); H[3] = make_float2(u1.z, u1.w);
        }
        dft4(G);   // G[q3] = 0.5 * Z[512*q3 + ca]
        dft4(H);   // H[q3] = 0.5 * Z[512*q3 + cb]

        int    bins[4];
        float2 zf[4], zg[4];
        zf[0] = G[0]; zf[1] = G[1]; zf[2] = H[0]; zf[3] = H[1];
        if (t) {
            bins[0] = t;        zg[0] = H[3];   // Z[2048-t]
            bins[1] = t + 512;  zg[1] = H[2];   // Z[1536-t]
            bins[2] = 512 - t;  zg[2] = G[3];   // Z[1536+t]
            bins[3] = 1024 - t; zg[3] = G[2];   // Z[1024+t]
        } else {
            bins[0] = 0;   zg[0] = G[0];
            bins[1] = 512; zg[1] = G[3];
            bins[2] = 256; zg[2] = H[3];
            bins[3] = 768; zg[3] = H[2];
        }

        float* outR = out;
        float* outI = out + (size_t)(BATCH * FRAMES) * FREQ;
        size_t oA = (size_t)m0 * FREQ;
        size_t oB = (size_t)m1 * FREQ;
        #pragma unroll
        for (int i = 0; i < 4; i++) {
            int f = bins[i];
            float2 S = cadd(zf[i], zg[i]);   // (outRA, outRB)
            float2 D = csub(zg[i], zf[i]);   // (outIB, -outIA)
            outR[oA + f] = S.x;
            outR[oB + f] = S.y;
            outI[oA + f] = -D.y;
            outI[oB + f] = D.x;
        }
    }
}

extern "C" void kernel_launch(void* const* d_in, const int* in_sizes, int n_in,
                              void* d_out, int out_size)
{
    const float* x = (const float*)d_in[0];   // input_signal [64, 32256, 1]
    float* out = (float*)d_out;               // [2, 4032, 1024]
    stft_kernel<<<NPAIRS, NT>>>(x, out);
}

// round 16
// speedup vs baseline: 1.1379x; 1.1379x over previous
#include <cuda_runtime.h>
#include <cstdint>

// STFT via 2048-pt complex FFT (two real frames per FFT: A=re, B=im).
// R16: DIF radix 16-16-8, 128 threads x 16 elements. 4 smem sweeps,
// 2 syncthreads + 1 syncwarp, 2 sincos. Fused conjugate-split epilogue
// over the 256 final radix-8 groups (thread t owns groups {t, 256-t}).

#define WINDOW   2048
#define STRIDE   512
#define FREQ     1024
#define FRAMES   63
#define SIG_LEN  32256
#define BATCH    64
#define PAD_L    768
#define NT       128
#define NPAIRS   2016

__device__ __forceinline__ float2 cadd(float2 a, float2 b) {
    float2 r;
    asm("{\n\t.reg .b64 ra, rb, rc;\n\t"
        "mov.b64 ra, {%2, %3};\n\t"
        "mov.b64 rb, {%4, %5};\n\t"
        "add.rn.f32x2 rc, ra, rb;\n\t"
        "mov.b64 {%0, %1}, rc;\n\t}"
        : "=f"(r.x), "=f"(r.y)
        : "f"(a.x), "f"(a.y), "f"(b.x), "f"(b.y));
    return r;
}
__device__ __forceinline__ float2 csub(float2 a, float2 b) {
    float2 r;
    asm("{\n\t.reg .b64 ra, rb, rc;\n\t"
        "mov.b64 ra, {%2, %3};\n\t"
        "mov.b64 rb, {%4, %5};\n\t"
        "sub.rn.f32x2 rc, ra, rb;\n\t"
        "mov.b64 {%0, %1}, rc;\n\t}"
        : "=f"(r.x), "=f"(r.y)
        : "f"(a.x), "f"(a.y), "f"(b.x), "f"(b.y));
    return r;
}
__device__ __forceinline__ float2 cmul(float2 a, float2 b) {
    return make_float2(fmaf(a.x, b.x, -a.y * b.y), fmaf(a.x, b.y, a.y * b.x));
}
__device__ __forceinline__ float2 cnegi(float2 a) { return make_float2(a.y, -a.x); }

#define RSQ2 0.70710678118654752440f
#define C16  0.92387953251128676f
#define S16  0.38268343236508978f

__device__ __forceinline__ float2 mulW2(float2 a) {   // * (R,-R) = W16^2
    return make_float2(RSQ2 * (a.x + a.y), RSQ2 * (a.y - a.x));
}
__device__ __forceinline__ float2 mulW6(float2 a) {   // * (-R,-R) = W16^6
    return make_float2(RSQ2 * (a.y - a.x), -RSQ2 * (a.x + a.y));
}
__device__ __forceinline__ float2 cmulc(float2 a, float cr, float ci) {
    return make_float2(fmaf(a.x, cr, -a.y * ci), fmaf(a.x, ci, a.y * cr));
}

__device__ __forceinline__ void dft4r(float2& x0, float2& x1, float2& x2, float2& x3) {
    float2 A0 = cadd(x0, x2), A1 = cadd(x1, x3);
    float2 B0 = csub(x0, x2), B1 = cnegi(csub(x1, x3));
    x0 = cadd(A0, A1); x1 = cadd(B0, B1);
    x2 = csub(A0, A1); x3 = csub(B0, B1);
}

// 16-pt DFT, j = a + 4b in, X[c+4d] lands at E[4c+d].
__device__ __forceinline__ void dft16(float2* E) {
    dft4r(E[0], E[4], E[8],  E[12]);
    dft4r(E[1], E[5], E[9],  E[13]);
    dft4r(E[2], E[6], E[10], E[14]);
    dft4r(E[3], E[7], E[11], E[15]);
    E[5]  = cmulc(E[5],  C16, -S16);   // W16^1
    E[6]  = mulW2(E[6]);               // W16^2
    E[7]  = cmulc(E[7],  S16, -C16);   // W16^3
    E[9]  = mulW2(E[9]);
    E[10] = cnegi(E[10]);              // W16^4
    E[11] = mulW6(E[11]);              // W16^6
    E[13] = cmulc(E[13], S16, -C16);
    E[14] = mulW6(E[14]);
    E[15] = cmulc(E[15], -C16, S16);   // W16^9
    dft4r(E[0],  E[1],  E[2],  E[3]);
    dft4r(E[4],  E[5],  E[6],  E[7]);
    dft4r(E[8],  E[9],  E[10], E[11]);
    dft4r(E[12], E[13], E[14], E[15]);
}

__device__ __forceinline__ void dft8(float2* E) {
    const float R = RSQ2;
    float2 s0 = cadd(E[0], E[4]), s1 = cadd(E[1], E[5]);
    float2 s2 = cadd(E[2], E[6]), s3 = cadd(E[3], E[7]);
    float2 d0 = csub(E[0], E[4]), d1 = csub(E[1], E[5]);
    float2 d2 = csub(E[2], E[6]), d3 = csub(E[3], E[7]);
    d1 = make_float2(R * (d1.x + d1.y), R * (d1.y - d1.x));
    d2 = cnegi(d2);
    d3 = make_float2(R * (d3.y - d3.x), -R * (d3.x + d3.y));
    float2 A0 = cadd(s0, s2), A1 = cadd(s1, s3);
    float2 B0 = csub(s0, s2), B1 = cnegi(csub(s1, s3));
    E[0] = cadd(A0, A1); E[2] = cadd(B0, B1);
    E[4] = csub(A0, A1); E[6] = csub(B0, B1);
    float2 C0 = cadd(d0, d2), C1 = cadd(d1, d3);
    float2 D0 = csub(d0, d2), D1 = cnegi(csub(d1, d3));
    E[1] = cadd(C0, C1); E[3] = cadd(D0, D1);
    E[5] = csub(C0, C1); E[7] = csub(D0, D1);
}

// Apply w^q to X[q] = E[4(q&3)+(q>>2)], store at zz[addr(q)].
template <typename FA>
__device__ __forceinline__ void tw_store16(float2* zz, const float2* E, FA addr, float2 w) {
#define XQ(q) E[4 * ((q) & 3) + ((q) >> 2)]
    zz[addr(0)]  = XQ(0);
    zz[addr(1)]  = cmul(XQ(1), w);
    float2 w2 = cmul(w, w);   zz[addr(2)] = cmul(XQ(2), w2);
    float2 w3 = cmul(w2, w);  zz[addr(3)] = cmul(XQ(3), w3);
    float2 w4 = cmul(w2, w2);
    zz[addr(4)]  = cmul(XQ(4), w4);
    zz[addr(5)]  = cmul(XQ(5), cmul(w4, w));
    zz[addr(6)]  = cmul(XQ(6), cmul(w4, w2));
    zz[addr(7)]  = cmul(XQ(7), cmul(w4, w3));
    float2 w8 = cmul(w4, w4);
    zz[addr(8)]  = cmul(XQ(8), w8);
    zz[addr(9)]  = cmul(XQ(9), cmul(w8, w));
    zz[addr(10)] = cmul(XQ(10), cmul(w8, w2));
    zz[addr(11)] = cmul(XQ(11), cmul(w8, w3));
    float2 w12 = cmul(w8, w4);
    zz[addr(12)] = cmul(XQ(12), w12);
    zz[addr(13)] = cmul(XQ(13), cmul(w12, w));
    zz[addr(14)] = cmul(XQ(14), cmul(w12, w2));
    zz[addr(15)] = cmul(XQ(15), cmul(w12, w3));
#undef XQ
}

__global__ __launch_bounds__(NT, 7) void stft_kernel(const float* __restrict__ x,
                                                     float* __restrict__ out)
{
    __shared__ __align__(16) float2 zz[2048];

    const int t  = threadIdx.x;            // 0..127
    const int m0 = 2 * blockIdx.x, m1 = m0 + 1;
    const int ba = m0 / FRAMES, fa = m0 - ba * FRAMES;
    const int bb = m1 / FRAMES, fb = m1 - bb * FRAMES;
    const float* xA = x + ba * SIG_LEN;
    const float* xB = x + bb * SIG_LEN;
    const int baseA = fa * STRIDE - PAD_L;
    const int baseB = fb * STRIDE - PAD_L;

    float2 E[16];

    // ---- pass 0: load x[t+128j] coalesced, half-Hann, dft16 over j,
    // twiddle W2048^{t q}, store y[q][t] at 128q + (t ^ 8(q&1)).
    {
        float sn0, cs0;
        __sincosf(3.06796157577128245e-3f * (float)t, &sn0, &cs0);  // 2*pi*t/2048
        const float CJ[8] = {1.0f,  C16,  RSQ2,  S16, 0.0f, -S16, -RSQ2, -C16};
        const float SJ[8] = {0.0f,  S16,  RSQ2,  C16, 1.0f,  C16,  RSQ2,  S16};
        const bool interior = (baseA >= 0) && (baseA <= SIG_LEN - WINDOW) &&
                              (baseB >= 0) && (baseB <= SIG_LEN - WINDOW);
        #pragma unroll
        for (int j = 0; j < 8; j++) {
            // 0.5*hann(t+128j) = 0.25 - 0.25(cs0*CJ - sn0*SJ); w(j+8) = 0.5 - w(j)
            float w0 = fmaf(sn0, 0.25f * SJ[j], fmaf(cs0, -0.25f * CJ[j], 0.25f));
            float w1 = 0.5f - w0;
            int i0 = t + 128 * j, i1 = i0 + 1024;
            float va0, vb0, va1, vb1;
            if (interior) {
                va0 = xA[baseA + i0]; vb0 = xB[baseB + i0];
                va1 = xA[baseA + i1]; vb1 = xB[baseB + i1];
            } else {
                int a0 = baseA + i0, a1 = baseA + i1, b0 = baseB + i0, b1i = baseB + i1;
                va0 = ((unsigned)a0 < (unsigned)SIG_LEN) ? xA[a0] : 0.0f;
                va1 = ((unsigned)a1 < (unsigned)SIG_LEN) ? xA[a1] : 0.0f;
                vb0 = ((unsigned)b0 < (unsigned)SIG_LEN) ? xB[b0] : 0.0f;
                vb1 = ((unsigned)b1i < (unsigned)SIG_LEN) ? xB[b1i] : 0.0f;
            }
            E[j]     = make_float2(w0 * va0, w0 * vb0);
            E[j + 8] = make_float2(w1 * va1, w1 * vb1);
        }
        dft16(E);
        tw_store16(zz, E,
                   [&](int q) { return 128 * q + (t ^ ((q & 1) << 3)); },
                   make_float2(cs0, -sn0));   // W_2048^t
    }
    __syncthreads();

    // ---- pass 1: thread (q=t>>3, n2=t&7) reads y[q][n2+8j], dft16,
    // twiddle W128^{n2 q2}, stores z at 128q + 8(q2^(q&1)) + (n2^(q>>1)).
    {
        int q = t >> 3, n2 = t & 7, b1 = q & 1, e1 = q >> 1;
        int rbase = 128 * q + n2;
        #pragma unroll
        for (int j = 0; j < 16; j++) E[j] = zz[rbase + 8 * (j ^ b1)];
        __syncwarp();   // in-place within warp: all reads before any store
        dft16(E);
        float2 w; __sincosf(-4.90873852123405191e-2f * (float)n2, &w.y, &w.x); // W_128^n2
        int A = 128 * q + (n2 ^ e1);
        tw_store16(zz, E, [&](int q2) { return A + 8 * (q2 ^ b1); }, w);
    }
    __syncthreads();

    // ---- pass 2 (radix-8) + fused conjugate-split epilogue.
    // Bin f = c + 256*m3, group c = q + 16*q2. Thread t owns ca=t and
    // cb = t ? 256-t : 128, so Z[f] <-> Z[2048-f] pair in registers.
    {
        float2* G = E; float2* H = E + 8;
        int ca = t;
        int cb = t ? (256 - t) : 128;
        {
            int q = ca & 15, q2 = ca >> 4, e = q >> 1;
            int g = 128 * q + 8 * (q2 ^ (q & 1));
            #pragma unroll
            for (int n = 0; n < 8; n++) G[n] = zz[g + (n ^ e)];
        }
        {
            int q = cb & 15, q2 = cb >> 4, e = q >> 1;
            int g = 128 * q + 8 * (q2 ^ (q & 1));
            #pragma unroll
            for (int n = 0; n < 8; n++) H[n] = zz[g + (n ^ e)];
        }
        dft8(G);   // G[m3] = 0.5*Z[ca + 256*m3]
        dft8(H);   // H[m3] = 0.5*Z[cb + 256*m3]

        float2 zga[4], zgb[4];
        if (t) {
            #pragma unroll
            for (int i = 0; i < 4; i++) { zga[i] = H[7 - i]; zgb[i] = G[7 - i]; }
        } else {
            zga[0] = G[0]; zga[1] = G[7]; zga[2] = G[6]; zga[3] = G[5];
            #pragma unroll
            for (int i = 0; i < 4; i++) zgb[i] = H[7 - i];
        }

        float* outR = out;
        float* outI = out + (size_t)(BATCH * FRAMES) * FREQ;
        size_t oA = (size_t)m0 * FREQ;
        size_t oB = (size_t)m1 * FREQ;
        #pragma unroll
        for (int i = 0; i < 4; i++) {
            int fA = t + 256 * i;
            float2 S = cadd(G[i], zga[i]);
            float2 D = csub(zga[i], G[i]);
            outR[oA + fA] = S.x;  outR[oB + fA] = S.y;
            outI[oA + fA] = -D.y; outI[oB + fA] = D.x;
            int fB = cb + 256 * i;
            float2 S2 = cadd(H[i], zgb[i]);
            float2 D2 = csub(zgb[i], H[i]);
            outR[oA + fB] = S2.x;  outR[oB + fB] = S2.y;
            outI[oA + fB] = -D2.y; outI[oB + fB] = D2.x;
        }
    }
}

extern "C" void kernel_launch(void* const* d_in, const int* in_sizes, int n_in,
                              void* d_out, int out_size)
{
    const float* x = (const float*)d_in[0];   // input_signal [64, 32256, 1]
    float* out = (float*)d_out;               // [2, 4032, 1024]
    stft_kernel<<<NPAIRS, NT>>>(x, out);
}